// round 8
// baseline (speedup 1.0000x reference)
#include <cuda_runtime.h>
#include <cuda_bf16.h>
#include <math.h>

#define DDIM  512
#define PCNT  64
#define CCNT  100
#define NBOX  4096
#define G     8
#define MAXWORK 608

// ---- device scratch ----
__device__ float g_pT[CCNT * DDIM * PCNT];   // float2 view [C][256][64]
__device__ float g_psq[CCNT * PCNT];
__device__ int   g_off[CCNT];
__device__ int   g_cnt[CCNT];
__device__ int   g_sorted[NBOX];
__device__ int   g_work[MAXWORK];            // (c << 8) | tile
__device__ int   g_nwork;

// =======================================================================
// prep: blocks 0..99 transpose protos for class c + psq; block 100 sorts
// =======================================================================
__global__ __launch_bounds__(256) void prep_kernel(
    const float* __restrict__ protos,
    const int*   __restrict__ cls_ids)
{
    const int tid = threadIdx.x;

    if (blockIdx.x == CCNT) {
        // -------- sort block --------
        __shared__ int hist[CCNT];
        __shared__ int off[CCNT];
        __shared__ int cur[CCNT];
        __shared__ short ids[NBOX];          // 8 KB

        if (tid < CCNT) hist[tid] = 0;
        __syncthreads();
        for (int i = tid; i < NBOX; i += 256) {
            int cc = cls_ids[i];
            ids[i] = (short)cc;
            atomicAdd(&hist[cc], 1);
        }
        __syncthreads();
        if (tid == 0) {
            int run = 0, k = 0;
            for (int c = 0; c < CCNT; c++) {
                int h = hist[c];
                off[c] = run;
                g_off[c] = run;
                g_cnt[c] = h;
                run += h;
                int nt = (h + G - 1) / G;
                for (int t = 0; t < nt; t++) g_work[k++] = (c << 8) | t;
            }
            g_nwork = k;
        }
        __syncthreads();
        if (tid < CCNT) cur[tid] = off[tid];
        __syncthreads();
        for (int i = tid; i < NBOX; i += 256) {
            int cc = ids[i];
            int pos = atomicAdd(&cur[cc], 1);
            g_sorted[pos] = i;
        }
        return;
    }

    // -------- transpose + psq for class c --------
    const int c = blockIdx.x;
    __shared__ float buf[16][DDIM + 2];      // ~33 KB, pad kills bank conflicts

    #pragma unroll 1
    for (int chunk = 0; chunk < 4; chunk++) {
        const int p0 = chunk * 16;
        // load 16 proto rows, coalesced
        const float* src = protos + ((size_t)(c * PCNT + p0)) * DDIM;
        for (int i = tid; i < 16 * DDIM; i += 256) {
            int r = i >> 9, col = i & (DDIM - 1);
            buf[r][col] = src[(size_t)r * DDIM + col];
        }
        __syncthreads();

        // psq: warp w -> rows w, w+8
        {
            const int lane = tid & 31, w = tid >> 5;
            #pragma unroll
            for (int rr = 0; rr < 2; rr++) {
                int row = w + 8 * rr;
                float s = 0.f;
                #pragma unroll
                for (int j = 0; j < 16; j++) {
                    float v = buf[row][lane + 32 * j];
                    s += v * v;
                }
                #pragma unroll
                for (int o = 16; o > 0; o >>= 1) s += __shfl_down_sync(0xffffffffu, s, o);
                if (lane == 0) g_psq[c * PCNT + p0 + row] = s;
            }
        }

        // write transposed: for d2, 32 consecutive floats = 16 protos x 2 dims
        float* dstbase = g_pT + ((size_t)c * 256) * (PCNT * 2) + p0 * 2;
        for (int i = tid; i < 16 * DDIM; i += 256) {
            int d2 = i >> 5, r = i & 31;
            dstbase[(size_t)d2 * (PCNT * 2) + r] = buf[r >> 1][2 * d2 + (r & 1)];
        }
        __syncthreads();
    }
}

// =======================================================================
// main: one block = one (class, tile) from the compacted worklist
// =======================================================================
__global__ __launch_bounds__(256) void proto_match_kernel(
    const float* __restrict__ feats,
    const int*   __restrict__ plabels,
    float* __restrict__ out,
    int N)
{
    if ((int)blockIdx.x >= g_nwork) return;
    const int wk   = g_work[blockIdx.x];
    const int c    = wk >> 8;
    const int tile = wk & 0xff;
    const int cnt  = g_cnt[c];
    const int cnt_tile = min(G, cnt - tile * G);
    const int start0 = g_off[c] + tile * G;

    const int tid  = threadIdx.x;
    const int lane = tid & 31;
    const int wid  = tid >> 5;
    const int p    = tid & 63;
    const int bq   = tid >> 6;

    __shared__ float f[G][DDIM];
    __shared__ float dot_sh[G][PCNT];
    __shared__ float l1_sh[G][PCNT];
    __shared__ float fsq_sh[G];

    // stage G feature vectors (warp w -> box w) + ||f||^2
    {
        int nb = g_sorted[start0 + min(wid, cnt_tile - 1)];
        const float4* src = reinterpret_cast<const float4*>(feats + (size_t)nb * DDIM);
        float4* dst = reinterpret_cast<float4*>(&f[wid][0]);
        float sq = 0.f;
        #pragma unroll
        for (int j = 0; j < 4; j++) {
            float4 v = __ldg(&src[lane + 32 * j]);
            dst[lane + 32 * j] = v;
            sq += v.x*v.x + v.y*v.y + v.z*v.z + v.w*v.w;
        }
        #pragma unroll
        for (int o = 16; o > 0; o >>= 1) sq += __shfl_down_sync(0xffffffffu, sq, o);
        if (lane == 0) fsq_sh[wid] = sq;
    }
    __syncthreads();

    // main loop: thread owns proto p x boxes (2bq, 2bq+1)
    const int b0 = 2 * bq, b1 = 2 * bq + 1;
    const float2* pt = reinterpret_cast<const float2*>(g_pT)
                       + (size_t)c * (256 * PCNT) + p;
    const float* fb0 = &f[b0][0];
    const float* fb1 = &f[b1][0];

    float dot0 = 0.f, dot1 = 0.f, l10 = 0.f, l11 = 0.f;
    #pragma unroll 4
    for (int d2 = 0; d2 < 256; d2 += 2) {
        float2 q0 = __ldg(&pt[(size_t)d2 * PCNT]);
        float2 q1 = __ldg(&pt[(size_t)(d2 + 1) * PCNT]);
        float4 fa = *reinterpret_cast<const float4*>(fb0 + 2 * d2);
        float4 fc = *reinterpret_cast<const float4*>(fb1 + 2 * d2);
        dot0 += q0.x*fa.x + q0.y*fa.y + q1.x*fa.z + q1.y*fa.w;
        l10  += fabsf(fa.x - q0.x) + fabsf(fa.y - q0.y)
              + fabsf(fa.z - q1.x) + fabsf(fa.w - q1.y);
        dot1 += q0.x*fc.x + q0.y*fc.y + q1.x*fc.z + q1.y*fc.w;
        l11  += fabsf(fc.x - q0.x) + fabsf(fc.y - q0.y)
              + fabsf(fc.z - q1.x) + fabsf(fc.w - q1.y);
    }
    dot_sh[b0][p] = dot0;  dot_sh[b1][p] = dot1;
    l1_sh[b0][p]  = l10;   l1_sh[b1][p]  = l11;
    __syncthreads();

    // epilogue: warp w -> box w
    {
        const int b = wid;
        const bool valid = (b < cnt_tile);
        const int n = g_sorted[start0 + (valid ? b : 0)];
        const float fsq   = fsq_sh[b];
        const float fnorm = fmaxf(sqrtf(fsq), 1e-8f);

        float dt0 = dot_sh[b][lane], dt1 = dot_sh[b][lane + 32];
        float la0 = l1_sh[b][lane],  la1 = l1_sh[b][lane + 32];
        float ps0 = g_psq[c * PCNT + lane], ps1 = g_psq[c * PCNT + lane + 32];
        float pn0 = fmaxf(sqrtf(ps0), 1e-8f), pn1 = fmaxf(sqrtf(ps1), 1e-8f);

        float dd0[3], dd1[3];
        dd0[0] = 1.f - dt0 / (fnorm * pn0);
        dd1[0] = 1.f - dt1 / (fnorm * pn1);
        dd0[1] = la0 * (1.f / DDIM);
        dd1[1] = la1 * (1.f / DDIM);
        dd0[2] = (fsq - 2.f * dt0 + ps0) * (1.f / DDIM);
        dd1[2] = (fsq - 2.f * dt1 + ps1) * (1.f / DDIM);

        float avg0 = 0.f, avg1 = 0.f;
        #pragma unroll
        for (int m = 0; m < 3; m++) {
            float s0 = 1.f / (dd0[m] + 1e-5f);
            float s1 = 1.f / (dd1[m] + 1e-5f);
            float mx = fmaxf(s0, s1);
            #pragma unroll
            for (int o = 16; o > 0; o >>= 1) mx = fmaxf(mx, __shfl_xor_sync(0xffffffffu, mx, o));
            float e0 = expf(s0 - mx), e1 = expf(s1 - mx);
            float sum = e0 + e1;
            #pragma unroll
            for (int o = 16; o > 0; o >>= 1) sum += __shfl_xor_sync(0xffffffffu, sum, o);
            float inv = 1.f / sum;
            avg0 += e0 * inv;
            avg1 += e1 * inv;
        }
        avg0 *= (1.f / 3.f);
        avg1 *= (1.f / 3.f);

        if (valid) {
            out[(size_t)N + (size_t)n * PCNT + lane]      = avg0;
            out[(size_t)N + (size_t)n * PCNT + lane + 32] = avg1;
        }

        float a0 = avg0; int i0 = lane;
        if (avg1 > a0) { a0 = avg1; i0 = lane + 32; }
        #pragma unroll
        for (int o = 16; o > 0; o >>= 1) {
            float ao = __shfl_xor_sync(0xffffffffu, a0, o);
            int   io = __shfl_xor_sync(0xffffffffu, i0, o);
            if (ao > a0 || (ao == a0 && io < i0)) { a0 = ao; i0 = io; }
        }
        if (lane == 0 && valid) out[n] = (float)plabels[c * PCNT + i0];
    }
}

extern "C" void kernel_launch(void* const* d_in, const int* in_sizes, int n_in,
                              void* d_out, int out_size) {
    const float* feats   = (const float*)d_in[0];   // [N, 512]
    const float* protos  = (const float*)d_in[1];   // [100, 64, 512]
    const int*   cls_ids = (const int*)d_in[2];     // [N]
    const int*   plabels = (const int*)d_in[3];     // [100, 64]
    float* out = (float*)d_out;

    int N = in_sizes[0] / DDIM;   // 4096

    prep_kernel<<<CCNT + 1, 256>>>(protos, cls_ids);
    proto_match_kernel<<<MAXWORK, 256>>>(feats, plabels, out, N);
}

// round 9
// speedup vs baseline: 1.1905x; 1.1905x over previous
#include <cuda_runtime.h>
#include <cuda_bf16.h>
#include <math.h>

#define DDIM  512
#define PCNT  64
#define CCNT  100
#define NBOX  4096
#define G     8
#define MAXWORK 608

typedef unsigned long long ull;

#define FFMA2(d,a,b,c) asm("fma.rn.f32x2 %0, %1, %2, %3;" : "=l"(d) : "l"(a), "l"(b), "l"(c))
#define FADD2(d,a,b)   asm("add.rn.f32x2 %0, %1, %2;" : "=l"(d) : "l"(a), "l"(b))

__device__ __forceinline__ float pair_sum(ull v) {
    float lo, hi;
    asm("mov.b64 {%0, %1}, %2;" : "=f"(lo), "=f"(hi) : "l"(v));
    return lo + hi;
}

#define MASK2 0x7FFFFFFF7FFFFFFFULL
#define NEG1P 0xBF800000BF800000ULL

// ---- device scratch ----
__device__ float g_pT[CCNT * DDIM * PCNT];   // float2 view [C][256 d2][64 p]
__device__ float g_psq[CCNT * PCNT];
__device__ int   g_off[CCNT];
__device__ int   g_cnt[CCNT];
__device__ int   g_sorted[NBOX];
__device__ int   g_work[MAXWORK];            // (c << 8) | tile
__device__ int   g_nwork;

// =======================================================================
// prep: blocks 0..99 transpose protos for class c + psq; block 100 sorts
// =======================================================================
__global__ __launch_bounds__(256) void prep_kernel(
    const float* __restrict__ protos,
    const int*   __restrict__ cls_ids)
{
    const int tid = threadIdx.x;

    if (blockIdx.x == CCNT) {
        __shared__ int hist[CCNT];
        __shared__ int off[CCNT];
        __shared__ int cur[CCNT];
        __shared__ short ids[NBOX];

        if (tid < CCNT) hist[tid] = 0;
        __syncthreads();
        for (int i = tid; i < NBOX; i += 256) {
            int cc = cls_ids[i];
            ids[i] = (short)cc;
            atomicAdd(&hist[cc], 1);
        }
        __syncthreads();
        if (tid == 0) {
            int run = 0, k = 0;
            for (int c = 0; c < CCNT; c++) {
                int h = hist[c];
                off[c] = run;
                g_off[c] = run;
                g_cnt[c] = h;
                run += h;
                int nt = (h + G - 1) / G;
                for (int t = 0; t < nt; t++) g_work[k++] = (c << 8) | t;
            }
            g_nwork = k;
        }
        __syncthreads();
        if (tid < CCNT) cur[tid] = off[tid];
        __syncthreads();
        for (int i = tid; i < NBOX; i += 256) {
            int cc = ids[i];
            int pos = atomicAdd(&cur[cc], 1);
            g_sorted[pos] = i;
        }
        return;
    }

    // transpose + psq for class c
    const int c = blockIdx.x;
    __shared__ float buf[16][DDIM + 2];

    #pragma unroll 1
    for (int chunk = 0; chunk < 4; chunk++) {
        const int p0 = chunk * 16;
        const float* src = protos + ((size_t)(c * PCNT + p0)) * DDIM;
        for (int i = tid; i < 16 * DDIM; i += 256) {
            int r = i >> 9, col = i & (DDIM - 1);
            buf[r][col] = src[(size_t)r * DDIM + col];
        }
        __syncthreads();

        {
            const int lane = tid & 31, w = tid >> 5;
            #pragma unroll
            for (int rr = 0; rr < 2; rr++) {
                int row = w + 8 * rr;
                float s = 0.f;
                #pragma unroll
                for (int j = 0; j < 16; j++) {
                    float v = buf[row][lane + 32 * j];
                    s += v * v;
                }
                #pragma unroll
                for (int o = 16; o > 0; o >>= 1) s += __shfl_down_sync(0xffffffffu, s, o);
                if (lane == 0) g_psq[c * PCNT + p0 + row] = s;
            }
        }

        float* dstbase = g_pT + ((size_t)c * 256) * (PCNT * 2) + p0 * 2;
        for (int i = tid; i < 16 * DDIM; i += 256) {
            int d2 = i >> 5, r = i & 31;
            dstbase[(size_t)d2 * (PCNT * 2) + r] = buf[r >> 1][2 * d2 + (r & 1)];
        }
        __syncthreads();
    }
}

// =======================================================================
// main: block = (class, tile of 8 boxes); warp = (box-pair, d-half);
// lane owns protos {2*lane, 2*lane+1}; f32x2-packed 2x2 register tile
// =======================================================================
__global__ __launch_bounds__(256) void proto_match_kernel(
    const float* __restrict__ feats,
    const int*   __restrict__ plabels,
    float* __restrict__ out,
    int N)
{
    if ((int)blockIdx.x >= g_nwork) return;
    const int wk   = g_work[blockIdx.x];
    const int c    = wk >> 8;
    const int tile = wk & 0xff;
    const int cnt  = g_cnt[c];
    const int cnt_tile = min(G, cnt - tile * G);
    const int start0 = g_off[c] + tile * G;

    const int tid  = threadIdx.x;
    const int lane = tid & 31;
    const int wid  = tid >> 5;
    const int bp   = wid >> 1;      // box pair 0..3
    const int h    = wid & 1;       // d-half

    __shared__ float4 fpack[4][256];     // [pair][d2]: {f_b0.lo, f_b0.hi, f_b1.lo, f_b1.hi}
    __shared__ float dotp[2][G][PCNT];
    __shared__ float l1p[2][G][PCNT];
    __shared__ float fsq_sh[G];

    // ---- stage: warp w loads box w's feature row into fpack + ||f||^2 ----
    {
        const int b = wid, pr = b >> 1, side = b & 1;
        int nb = g_sorted[start0 + min(b, cnt_tile - 1)];
        const float4* src = reinterpret_cast<const float4*>(feats + (size_t)nb * DDIM);
        float sq = 0.f;
        #pragma unroll
        for (int j = 0; j < 4; j++) {
            float4 v = __ldg(&src[lane + 32 * j]);
            sq += v.x*v.x + v.y*v.y + v.z*v.z + v.w*v.w;
            int d2a = 2 * (lane + 32 * j);
            *reinterpret_cast<float2*>(&fpack[pr][d2a].x     + 2 * side) = make_float2(v.x, v.y);
            *reinterpret_cast<float2*>(&fpack[pr][d2a + 1].x + 2 * side) = make_float2(v.z, v.w);
        }
        #pragma unroll
        for (int o = 16; o > 0; o >>= 1) sq += __shfl_down_sync(0xffffffffu, sq, o);
        if (lane == 0) fsq_sh[wid] = sq;
    }
    __syncthreads();

    // ---- main loop ----
    ull da00 = 0, da01 = 0, da10 = 0, da11 = 0;   // dot[box][proto]
    ull la00 = 0, la01 = 0, la10 = 0, la11 = 0;   // l1 [box][proto]

    const ulonglong2* ptV = reinterpret_cast<const ulonglong2*>(g_pT)
                            + (size_t)c * (256 * 32) + lane;
    const ulonglong2* fpV = reinterpret_cast<const ulonglong2*>(&fpack[bp][0]);

    const int d2base = h * 128;
    #pragma unroll 4
    for (int i = 0; i < 128; i++) {
        const int d2 = d2base + i;
        ulonglong2 q  = __ldg(&ptV[(size_t)d2 * 32]);   // .x = proto 2*lane, .y = 2*lane+1
        ulonglong2 ff = fpV[d2];                         // .x = box b0 pair, .y = box b1 pair
        FFMA2(da00, q.x, ff.x, da00);
        FFMA2(da01, q.y, ff.x, da01);
        FFMA2(da10, q.x, ff.y, da10);
        FFMA2(da11, q.y, ff.y, da11);
        ull t0, t1, t2, t3;
        FFMA2(t0, q.x, NEG1P, ff.x); t0 &= MASK2; FADD2(la00, la00, t0);
        FFMA2(t1, q.y, NEG1P, ff.x); t1 &= MASK2; FADD2(la01, la01, t1);
        FFMA2(t2, q.x, NEG1P, ff.y); t2 &= MASK2; FADD2(la10, la10, t2);
        FFMA2(t3, q.y, NEG1P, ff.y); t3 &= MASK2; FADD2(la11, la11, t3);
    }

    // ---- write d-half partials ----
    {
        const int b0 = 2 * bp, b1 = 2 * bp + 1;
        const int p0 = 2 * lane, p1 = 2 * lane + 1;
        dotp[h][b0][p0] = pair_sum(da00);  dotp[h][b0][p1] = pair_sum(da01);
        dotp[h][b1][p0] = pair_sum(da10);  dotp[h][b1][p1] = pair_sum(da11);
        l1p[h][b0][p0]  = pair_sum(la00);  l1p[h][b0][p1]  = pair_sum(la01);
        l1p[h][b1][p0]  = pair_sum(la10);  l1p[h][b1][p1]  = pair_sum(la11);
    }
    __syncthreads();

    // ---- epilogue: warp w -> box w ----
    {
        const int b = wid;
        const bool valid = (b < cnt_tile);
        const int n = g_sorted[start0 + (valid ? b : 0)];
        const float fsq   = fsq_sh[b];
        const float fnorm = fmaxf(sqrtf(fsq), 1e-8f);

        float dt0 = dotp[0][b][lane]      + dotp[1][b][lane];
        float dt1 = dotp[0][b][lane + 32] + dotp[1][b][lane + 32];
        float la0 = l1p[0][b][lane]       + l1p[1][b][lane];
        float la1 = l1p[0][b][lane + 32]  + l1p[1][b][lane + 32];
        float ps0 = g_psq[c * PCNT + lane], ps1 = g_psq[c * PCNT + lane + 32];
        float pn0 = fmaxf(sqrtf(ps0), 1e-8f), pn1 = fmaxf(sqrtf(ps1), 1e-8f);

        float dd0[3], dd1[3];
        dd0[0] = 1.f - dt0 / (fnorm * pn0);
        dd1[0] = 1.f - dt1 / (fnorm * pn1);
        dd0[1] = la0 * (1.f / DDIM);
        dd1[1] = la1 * (1.f / DDIM);
        dd0[2] = (fsq - 2.f * dt0 + ps0) * (1.f / DDIM);
        dd1[2] = (fsq - 2.f * dt1 + ps1) * (1.f / DDIM);

        float avg0 = 0.f, avg1 = 0.f;
        #pragma unroll
        for (int m = 0; m < 3; m++) {
            float s0 = 1.f / (dd0[m] + 1e-5f);
            float s1 = 1.f / (dd1[m] + 1e-5f);
            float mx = fmaxf(s0, s1);
            #pragma unroll
            for (int o = 16; o > 0; o >>= 1) mx = fmaxf(mx, __shfl_xor_sync(0xffffffffu, mx, o));
            float e0 = expf(s0 - mx), e1 = expf(s1 - mx);
            float sum = e0 + e1;
            #pragma unroll
            for (int o = 16; o > 0; o >>= 1) sum += __shfl_xor_sync(0xffffffffu, sum, o);
            float inv = 1.f / sum;
            avg0 += e0 * inv;
            avg1 += e1 * inv;
        }
        avg0 *= (1.f / 3.f);
        avg1 *= (1.f / 3.f);

        if (valid) {
            out[(size_t)N + (size_t)n * PCNT + lane]      = avg0;
            out[(size_t)N + (size_t)n * PCNT + lane + 32] = avg1;
        }

        float a0 = avg0; int i0 = lane;
        if (avg1 > a0) { a0 = avg1; i0 = lane + 32; }
        #pragma unroll
        for (int o = 16; o > 0; o >>= 1) {
            float ao = __shfl_xor_sync(0xffffffffu, a0, o);
            int   io = __shfl_xor_sync(0xffffffffu, i0, o);
            if (ao > a0 || (ao == a0 && io < i0)) { a0 = ao; i0 = io; }
        }
        if (lane == 0 && valid) out[n] = (float)plabels[c * PCNT + i0];
    }
}

extern "C" void kernel_launch(void* const* d_in, const int* in_sizes, int n_in,
                              void* d_out, int out_size) {
    const float* feats   = (const float*)d_in[0];   // [N, 512]
    const float* protos  = (const float*)d_in[1];   // [100, 64, 512]
    const int*   cls_ids = (const int*)d_in[2];     // [N]
    const int*   plabels = (const int*)d_in[3];     // [100, 64]
    float* out = (float*)d_out;

    int N = in_sizes[0] / DDIM;   // 4096

    prep_kernel<<<CCNT + 1, 256>>>(protos, cls_ids);
    proto_match_kernel<<<MAXWORK, 256>>>(feats, plabels, out, N);
}